// round 14
// baseline (speedup 1.0000x reference)
#include <cuda_runtime.h>
#include <cuda_fp16.h>
#include <cuda_bf16.h>
#include <cstdint>

// Problem constants
#define C_DIM   192
#define HEADS   8
#define HD      24          // head dim = 192/8
#define HH      64
#define WW      64
#define NPIX    4096        // 64*64
#define QKV_CH  576         // 3*C

// ---------------- scratch (static device globals; no allocs) ----------------
__device__ float g_qkv[QKV_CH * NPIX];                // 9 MB (gemm1 out fp32)
__device__ float g_q32[C_DIM * NPIX];                 // 3 MB (dwconv Q out, fp32)
// LN output hi/lo fp16 [c][n]
__device__ unsigned short g_xh[C_DIM * NPIX];
__device__ unsigned short g_xl[C_DIM * NPIX];
// prepacked weights hi/lo fp16 [o][k]
__device__ unsigned short g_wqh[QKV_CH * C_DIM];
__device__ unsigned short g_wql[QKV_CH * C_DIM];
__device__ unsigned short g_wph[C_DIM * C_DIM];
__device__ unsigned short g_wpl[C_DIM * C_DIM];
// attention output hi/lo fp16 [c][n]
__device__ unsigned short g_ath[C_DIM * NPIX];
__device__ unsigned short g_atl[C_DIM * NPIX];
// prepacked K (hi/lo fp16, [head][key][32] cols 24..31 unused) and V fp16
__device__ unsigned short g_kh16[HEADS * NPIX * 32];
__device__ unsigned short g_kl16[HEADS * NPIX * 32];
__device__ unsigned short g_vh16[C_DIM * NPIX];

// ---------------- small helpers ----------------
__device__ __forceinline__ float ex2f_fast(float x) {
    float r;
    asm("ex2.approx.f32 %0, %1;" : "=f"(r) : "f"(x));
    return r;
}

__device__ __forceinline__ uint32_t h2ex2(uint32_t x) {
    uint32_t r;
    asm("ex2.approx.f16x2 %0, %1;" : "=r"(r) : "r"(x));
    return r;
}

__device__ __forceinline__ void mma16816(float c[4], const uint32_t a[4],
                                         uint32_t b0, uint32_t b1) {
    asm volatile(
        "mma.sync.aligned.m16n8k16.row.col.f32.f16.f16.f32 "
        "{%0,%1,%2,%3}, {%4,%5,%6,%7}, {%8,%9}, {%0,%1,%2,%3};"
        : "+f"(c[0]), "+f"(c[1]), "+f"(c[2]), "+f"(c[3])
        : "r"(a[0]), "r"(a[1]), "r"(a[2]), "r"(a[3]), "r"(b0), "r"(b1));
}

__device__ __forceinline__ void ldsm_x4(uint32_t& r0, uint32_t& r1,
                                        uint32_t& r2, uint32_t& r3, uint32_t addr) {
    asm volatile("ldmatrix.sync.aligned.m8n8.x4.shared.b16 {%0,%1,%2,%3}, [%4];"
                 : "=r"(r0), "=r"(r1), "=r"(r2), "=r"(r3) : "r"(addr));
}

__device__ __forceinline__ void ldsm_x4_t(uint32_t& r0, uint32_t& r1,
                                          uint32_t& r2, uint32_t& r3, uint32_t addr) {
    asm volatile("ldmatrix.sync.aligned.m8n8.x4.trans.shared.b16 {%0,%1,%2,%3}, [%4];"
                 : "=r"(r0), "=r"(r1), "=r"(r2), "=r"(r3) : "r"(addr));
}

__device__ __forceinline__ void cp16(uint32_t dst, const void* src) {
    asm volatile("cp.async.cg.shared.global [%0], [%1], 16;"
                 :: "r"(dst), "l"(src));
}

__device__ __forceinline__ uint32_t packh2(float x, float y) {
    __half2 h = __floats2half2_rn(x, y);
    return *(uint32_t*)&h;
}

// ---------------- Kernel 1: LayerNorm -> hi/lo fp16 [c][n] ----------------
__global__ void ln_kernel(const float* __restrict__ x,
                          const float* __restrict__ gamma,
                          const float* __restrict__ beta,
                          unsigned short* __restrict__ xh,
                          unsigned short* __restrict__ xl) {
    int p = blockIdx.x * blockDim.x + threadIdx.x;
    if (p >= NPIX) return;
    float s = 0.f, s2 = 0.f;
    #pragma unroll 8
    for (int c = 0; c < C_DIM; c++) {
        float v = x[c * NPIX + p];
        s += v;
        s2 = fmaf(v, v, s2);
    }
    const float invC = 1.0f / (float)C_DIM;
    float mean = s * invC;
    float var = s2 * invC - mean * mean;
    float inv = rsqrtf(var + 1e-5f);
    #pragma unroll 8
    for (int c = 0; c < C_DIM; c++) {
        float v = (x[c * NPIX + p] - mean) * inv;
        v = fmaf(v, gamma[c], beta[c]);
        __half h = __float2half_rn(v);
        xh[c * NPIX + p] = __half_as_ushort(h);
        xl[c * NPIX + p] = __half_as_ushort(__float2half_rn(v - __half2float(h)));
    }
}

// ---------------- Kernel 1b: weight prepack (hi/lo fp16 split) ----------------
__global__ void wprep_kernel(const float* __restrict__ wq, const float* __restrict__ wp,
                             unsigned short* __restrict__ wqh, unsigned short* __restrict__ wql,
                             unsigned short* __restrict__ wph, unsigned short* __restrict__ wpl) {
    int i = blockIdx.x * 256 + threadIdx.x;
    if (i < QKV_CH * C_DIM) {
        float v = wq[i];
        __half h = __float2half_rn(v);
        wqh[i] = __half_as_ushort(h);
        wql[i] = __half_as_ushort(__float2half_rn(v - __half2float(h)));
    }
    if (i < C_DIM * C_DIM) {
        float v = wp[i];
        __half h = __float2half_rn(v);
        wph[i] = __half_as_ushort(h);
        wpl[i] = __half_as_ushort(__float2half_rn(v - __half2float(h)));
    }
}

// ---------------- Kernel 2: tensor-core GEMM (hi/lo fp16 compensated) ----------
__global__ __launch_bounds__(128) void gemm16_kernel(
        const unsigned short* __restrict__ Wh,
        const unsigned short* __restrict__ Wl,
        const unsigned short* __restrict__ Bh,
        const unsigned short* __restrict__ Bl,
        const float* __restrict__ resid,
        float* __restrict__ Y,
        int O, int K, int N) {
    __shared__ __align__(16) __half Wsh[64][40];
    __shared__ __align__(16) __half Wsl[64][40];
    __shared__ __align__(16) __half Xsh[32][72];
    __shared__ __align__(16) __half Xsl[32][72];
    const int tid = threadIdx.x;
    const int lane = tid & 31, warp = tid >> 5;
    const int g = lane >> 2, t = lane & 3;
    const int o0 = blockIdx.y * 64, n0 = blockIdx.x * 64;

    float acc[8][4];
    #pragma unroll
    for (int i = 0; i < 8; i++)
        #pragma unroll
        for (int j = 0; j < 4; j++) acc[i][j] = 0.f;

    const uint32_t xh_base = (uint32_t)__cvta_generic_to_shared(&Xsh[0][0])
                             + (uint32_t)(lane * 72) * 2;
    const uint32_t xl_base = (uint32_t)__cvta_generic_to_shared(&Xsl[0][0])
                             + (uint32_t)(lane * 72) * 2;

    for (int k0 = 0; k0 < K; k0 += 32) {
        if (k0) __syncthreads();
        {
            int row = tid >> 2, seg = tid & 3;
            #pragma unroll
            for (int rr = 0; rr < 2; rr++) {
                int r = row + rr * 32;
                *(uint4*)&Wsh[r][seg * 8] =
                    *(const uint4*)&Wh[(size_t)(o0 + r) * K + k0 + seg * 8];
                *(uint4*)&Wsl[r][seg * 8] =
                    *(const uint4*)&Wl[(size_t)(o0 + r) * K + k0 + seg * 8];
            }
            int xr = tid >> 3, xseg = tid & 7;
            #pragma unroll
            for (int rr = 0; rr < 2; rr++) {
                int k = xr + rr * 16;
                *(uint4*)&Xsh[k][xseg * 8] =
                    *(const uint4*)&Bh[(size_t)(k0 + k) * N + n0 + xseg * 8];
                *(uint4*)&Xsl[k][xseg * 8] =
                    *(const uint4*)&Bl[(size_t)(k0 + k) * N + n0 + xseg * 8];
            }
        }
        __syncthreads();

        uint32_t awh[2][4], awl[2][4];
        const int orr = warp * 16 + g;
        #pragma unroll
        for (int ks = 0; ks < 2; ks++) {
            int db = ks * 16 + t * 2;
            awh[ks][0] = *(const uint32_t*)&Wsh[orr][db];
            awh[ks][1] = *(const uint32_t*)&Wsh[orr + 8][db];
            awh[ks][2] = *(const uint32_t*)&Wsh[orr][db + 8];
            awh[ks][3] = *(const uint32_t*)&Wsh[orr + 8][db + 8];
            awl[ks][0] = *(const uint32_t*)&Wsl[orr][db];
            awl[ks][1] = *(const uint32_t*)&Wsl[orr + 8][db];
            awl[ks][2] = *(const uint32_t*)&Wsl[orr][db + 8];
            awl[ks][3] = *(const uint32_t*)&Wsl[orr + 8][db + 8];
        }
        #pragma unroll
        for (int nt = 0; nt < 8; nt++) {
            uint32_t bh0, bh1, bh2, bh3, bl0, bl1, bl2, bl3;
            ldsm_x4_t(bh0, bh1, bh2, bh3, xh_base + nt * 16);
            ldsm_x4_t(bl0, bl1, bl2, bl3, xl_base + nt * 16);
            mma16816(acc[nt], awh[0], bh0, bh1);
            mma16816(acc[nt], awh[1], bh2, bh3);
            mma16816(acc[nt], awh[0], bl0, bl1);
            mma16816(acc[nt], awh[1], bl2, bl3);
            mma16816(acc[nt], awl[0], bh0, bh1);
            mma16816(acc[nt], awl[1], bh2, bh3);
        }
    }

    const int orr = warp * 16 + g;
    #pragma unroll
    for (int nt = 0; nt < 8; nt++) {
        #pragma unroll
        for (int rr = 0; rr < 2; rr++) {
            int o = o0 + orr + rr * 8;
            int n = n0 + nt * 8 + t * 2;
            float v0 = acc[nt][rr * 2 + 0];
            float v1 = acc[nt][rr * 2 + 1];
            if (resid) {
                float2 rv = *(const float2*)&resid[(size_t)o * N + n];
                v0 += rv.x; v1 += rv.y;
            }
            float2 w2 = make_float2(v0, v1);
            *(float2*)&Y[(size_t)o * N + n] = w2;
        }
    }
}

// ---------------- Kernel 3: smem-tiled depthwise 3x3 conv + K/V prepack ----
// One CTA = one channel. 66x66 zero-padded smem tile; each thread computes a
// 16-pixel row segment (sliding-window FMAs on register-cached rows).
__global__ __launch_bounds__(256) void dwconv_kernel(
        const float* __restrict__ in,
        const float* __restrict__ w,
        const float* __restrict__ b,
        float* __restrict__ qout,
        unsigned short* __restrict__ kh,
        unsigned short* __restrict__ kl,
        unsigned short* __restrict__ vh) {
    __shared__ float tile[66 * 66];
    const int tid = threadIdx.x;
    const int ch = blockIdx.x;
    const float* base = &in[(size_t)ch * NPIX];

    // zero tile (covers padding borders)
    #pragma unroll
    for (int i = tid; i < 66 * 66; i += 256) tile[i] = 0.f;
    __syncthreads();
    // load 64x64 image into interior [1..64][1..64]
    #pragma unroll
    for (int i = tid; i < 1024; i += 256) {
        float4 v = ((const float4*)base)[i];
        int row = i >> 4;
        int col = (i & 15) * 4;
        float* dst = &tile[(row + 1) * 66 + col + 1];
        dst[0] = v.x; dst[1] = v.y; dst[2] = v.z; dst[3] = v.w;
    }
    __syncthreads();

    const float* wp = &w[ch * 9];
    float w00 = wp[0], w01 = wp[1], w02 = wp[2];
    float w10 = wp[3], w11 = wp[4], w12 = wp[5];
    float w20 = wp[6], w21 = wp[7], w22 = wp[8];
    float bias = b[ch];

    const int y = tid >> 2;            // output row 0..63
    const int xs = (tid & 3) * 16;     // output col start

    float r0[18], r1[18], r2[18];
    #pragma unroll
    for (int i = 0; i < 18; i++) {
        r0[i] = tile[y * 66 + xs + i];
        r1[i] = tile[(y + 1) * 66 + xs + i];
        r2[i] = tile[(y + 2) * 66 + xs + i];
    }

    float acc[16];
    #pragma unroll
    for (int k = 0; k < 16; k++) {
        float a = bias;
        a = fmaf(r0[k],     w00, a);
        a = fmaf(r0[k + 1], w01, a);
        a = fmaf(r0[k + 2], w02, a);
        a = fmaf(r1[k],     w10, a);
        a = fmaf(r1[k + 1], w11, a);
        a = fmaf(r1[k + 2], w12, a);
        a = fmaf(r2[k],     w20, a);
        a = fmaf(r2[k + 1], w21, a);
        a = fmaf(r2[k + 2], w22, a);
        acc[k] = a;
    }

    const int p0 = y * WW + xs;   // first output pixel index
    if (ch < C_DIM) {
        float* dst = &qout[(size_t)ch * NPIX + p0];
        #pragma unroll
        for (int k4 = 0; k4 < 4; k4++)
            *(float4*)&dst[k4 * 4] = make_float4(acc[k4 * 4], acc[k4 * 4 + 1],
                                                 acc[k4 * 4 + 2], acc[k4 * 4 + 3]);
    } else if (ch < 2 * C_DIM) {
        int cc = ch - C_DIM;
        int hh2 = cc / HD;
        int dd = cc % HD;
        unsigned short* khd = kh + ((size_t)(hh2 * NPIX + p0)) * 32 + dd;
        unsigned short* kld = kl + ((size_t)(hh2 * NPIX + p0)) * 32 + dd;
        #pragma unroll
        for (int k = 0; k < 16; k++) {
            __half hi = __float2half_rn(acc[k]);
            khd[(size_t)k * 32] = __half_as_ushort(hi);
            kld[(size_t)k * 32] =
                __half_as_ushort(__float2half_rn(acc[k] - __half2float(hi)));
        }
    } else {
        unsigned short* vd = vh + (size_t)(ch - 2 * C_DIM) * NPIX + p0;
        #pragma unroll
        for (int k8 = 0; k8 < 2; k8++) {
            uint4 pk;
            pk.x = packh2(acc[k8 * 8 + 0], acc[k8 * 8 + 1]);
            pk.y = packh2(acc[k8 * 8 + 2], acc[k8 * 8 + 3]);
            pk.z = packh2(acc[k8 * 8 + 4], acc[k8 * 8 + 5]);
            pk.w = packh2(acc[k8 * 8 + 6], acc[k8 * 8 + 7]);
            *(uint4*)&vd[k8 * 8] = pk;
        }
    }
}

// ---------------- Kernel 4: tensor-core flash attention ----------------
#define ATT_Q  128
#define ATT_K  128
#define NCHUNK (NPIX / ATT_K)         // 32

#define OKB  0
#define KBUF 10240
#define OVB  (3 * KBUF)               // 30720
#define VBUF 4352                     // 32*136
#define SM_HALVES (OVB + 3 * VBUF)    // 43776
#define SMEM_BYTES (SM_HALVES * 2)    // 87552

__global__ __launch_bounds__(256, 2) void attn_mma_kernel(
        const float* __restrict__ q32,
        const unsigned short* __restrict__ kh,
        const unsigned short* __restrict__ kl,
        const unsigned short* __restrict__ vh,
        const float* __restrict__ temp,
        unsigned short* __restrict__ attH,
        unsigned short* __restrict__ attL) {
    extern __shared__ __align__(16) __half sm[];
    const int tid = threadIdx.x;
    const int lane = tid & 31;
    const int warp = tid >> 5;
    const int g = lane >> 2;
    const int t = lane & 3;

    const int h = blockIdx.y;
    const int q0 = blockIdx.x * ATT_Q;
    const float scale = temp[h] * 1.4426950408889634f;

    const float* qg = q32 + (h * HD) * NPIX;
    const unsigned short* khg = kh + (size_t)h * NPIX * 32;
    const unsigned short* klg = kl + (size_t)h * NPIX * 32;
    const unsigned short* vg  = vh + (size_t)(h * HD) * NPIX;

    const uint32_t smb = (uint32_t)__cvta_generic_to_shared(sm);

    // one-time init: K pad cols 24..31 (all bufs), V rows 24..31
    {
        uint32_t* smw = (uint32_t*)sm;
        for (int i = tid; i < 3072; i += 256) {
            int wds = i & 3;
            int r2 = i >> 2;
            int buf = r2 >> 8;
            int rem = r2 & 255;
            int part = rem >> 7;
            int row = rem & 127;
            int halfoff = OKB + buf * KBUF + part * 5120 + row * 40 + 24;
            smw[(halfoff >> 1) + wds] = 0;
        }
        for (int i = tid; i < 3 * 8 * 136; i += 256) {
            int buf = i / 1088;
            int rem = i - buf * 1088;
            int row = rem / 136;
            int col = rem - row * 136;
            sm[OVB + buf * VBUF + (24 + row) * 136 + col] =
                (row == 0) ? __float2half_rn(1.0f) : __ushort_as_half(0);
        }
    }

    auto issue_chunk = [&](int b, int m0) {
        uint32_t kdstH = smb + (OKB + b * KBUF) * 2;
        uint32_t kdstL = kdstH + 5120 * 2;
        uint32_t vdst  = smb + (OVB + b * VBUF) * 2;
        #pragma unroll
        for (int i = tid; i < 1152; i += 256) {
            if (i < 768) {
                int r = i;
                int part = r >= 384;
                r -= part * 384;
                int key = r / 3;
                int c = r - key * 3;
                const unsigned short* src =
                    (part ? klg : khg) + (size_t)(m0 + key) * 32 + c * 8;
                uint32_t dst = (part ? kdstL : kdstH) + (key * 40 + c * 8) * 2;
                cp16(dst, src);
            } else {
                int r = i - 768;
                int d = r >> 4;
                int c2 = r & 15;
                const unsigned short* src = vg + (size_t)d * NPIX + m0 + c2 * 8;
                uint32_t dst = vdst + (d * 136 + c2 * 8) * 2;
                cp16(dst, src);
            }
        }
        asm volatile("cp.async.commit_group;" ::: "memory");
    };
    issue_chunk(0, 0);
    issue_chunk(1, ATT_K);

    // Q A-fragments directly from global
    uint32_t aqh[2][4], aql[2][4];
    const int qr = warp * 16 + g;
    #pragma unroll
    for (int ks = 0; ks < 2; ks++) {
        #pragma unroll
        for (int r = 0; r < 4; r++) {
            int d0 = ks * 16 + t * 2 + ((r >= 2) ? 8 : 0);
            int qq = q0 + qr + (r & 1) * 8;
            if (d0 < HD) {
                float v0 = qg[d0 * NPIX + qq] * scale;
                float v1 = qg[(d0 + 1) * NPIX + qq] * scale;
                __half h0 = __float2half_rn(v0);
                __half h1 = __float2half_rn(v1);
                aqh[ks][r] = ((uint32_t)__half_as_ushort(h1) << 16) |
                             __half_as_ushort(h0);
                __half l0 = __float2half_rn(v0 - __half2float(h0));
                __half l1 = __float2half_rn(v1 - __half2float(h1));
                aql[ks][r] = ((uint32_t)__half_as_ushort(l1) << 16) |
                             __half_as_ushort(l0);
            } else {
                aqh[ks][r] = 0;
                aql[ks][r] = 0;
            }
        }
    }

    const int l7 = lane & 7;
    const int grp = lane >> 3;
    const uint32_t loff_k = (l7 * 40 + grp * 8) * 2;
    const uint32_t loff_v = (l7 * 136 + grp * 8) * 2;

    float out[4][4];
    #pragma unroll
    for (int i = 0; i < 4; i++)
        #pragma unroll
        for (int j = 0; j < 4; j++) out[i][j] = 0.f;
    float m_a = -1e30f, m_b = -1e30f;

    for (int ch = 0; ch < NCHUNK; ch++) {
        if (ch < NCHUNK - 1)
            asm volatile("cp.async.wait_group 1;" ::: "memory");
        else
            asm volatile("cp.async.wait_group 0;" ::: "memory");
        __syncthreads();
        if (ch + 2 < NCHUNK) issue_chunk((ch + 2) % 3, (ch + 2) * ATT_K);

        const int b = ch % 3;
        const uint32_t kbase = smb + (OKB + b * KBUF) * 2;
        const uint32_t vbase = smb + (OVB + b * VBUF) * 2;

        #pragma unroll
        for (int hc = 0; hc < 2; hc++) {
            const uint32_t kaddr_h = kbase + (uint32_t)hc * 5120 + loff_k;
            const uint32_t kaddr_l = kaddr_h + 5120 * 2;
            const uint32_t vaddr   = vbase + (uint32_t)hc * 128 + loff_v;

            float s[8][4];
            #pragma unroll
            for (int nt = 0; nt < 8; nt++) {
                uint32_t h0, h1, h2, h3, L0, L1, L2, L3;
                ldsm_x4(h0, h1, h2, h3, kaddr_h + nt * 640);
                ldsm_x4(L0, L1, L2, L3, kaddr_l + nt * 640);
                s[nt][0] = s[nt][1] = s[nt][2] = s[nt][3] = 0.f;
                mma16816(s[nt], aqh[0], h0, h1);
                mma16816(s[nt], aqh[1], h2, h3);
                mma16816(s[nt], aql[0], h0, h1);
                mma16816(s[nt], aql[1], h2, h3);
                mma16816(s[nt], aqh[0], L0, L1);
                mma16816(s[nt], aqh[1], L2, L3);
            }

            float ra = -1e30f, rb = -1e30f;
            #pragma unroll
            for (int nt = 0; nt < 8; nt++) {
                ra = fmaxf(ra, fmaxf(s[nt][0], s[nt][1]));
                rb = fmaxf(rb, fmaxf(s[nt][2], s[nt][3]));
            }
            ra = fmaxf(ra, __shfl_xor_sync(0xffffffffu, ra, 1));
            ra = fmaxf(ra, __shfl_xor_sync(0xffffffffu, ra, 2));
            rb = fmaxf(rb, __shfl_xor_sync(0xffffffffu, rb, 1));
            rb = fmaxf(rb, __shfl_xor_sync(0xffffffffu, rb, 2));
            float nma = fmaxf(m_a, ra);
            float nmb = fmaxf(m_b, rb);
            float ala = ex2f_fast(m_a - nma);
            float alb = ex2f_fast(m_b - nmb);
            m_a = nma; m_b = nmb;
            #pragma unroll
            for (int dnt = 0; dnt < 4; dnt++) {
                out[dnt][0] *= ala; out[dnt][1] *= ala;
                out[dnt][2] *= alb; out[dnt][3] *= alb;
            }

            uint32_t pa[4][4];
            #pragma unroll
            for (int kv = 0; kv < 4; kv++) {
                pa[kv][0] = h2ex2(packh2(s[2 * kv][0] - m_a,     s[2 * kv][1] - m_a));
                pa[kv][1] = h2ex2(packh2(s[2 * kv][2] - m_b,     s[2 * kv][3] - m_b));
                pa[kv][2] = h2ex2(packh2(s[2 * kv + 1][0] - m_a, s[2 * kv + 1][1] - m_a));
                pa[kv][3] = h2ex2(packh2(s[2 * kv + 1][2] - m_b, s[2 * kv + 1][3] - m_b));
            }

            #pragma unroll
            for (int dnt = 0; dnt < 4; dnt++) {
                uint32_t base = vaddr + (uint32_t)(dnt * 8) * 272;
                uint32_t v0, v1, v2, v3, v4, v5, v6, v7;
                ldsm_x4(v0, v1, v2, v3, base);
                ldsm_x4(v4, v5, v6, v7, base + 64);
                mma16816(out[dnt], pa[0], v0, v1);
                mma16816(out[dnt], pa[1], v2, v3);
                mma16816(out[dnt], pa[2], v4, v5);
                mma16816(out[dnt], pa[3], v6, v7);
            }
        }
    }

    // epilogue: normalize, split hi/lo, store [c][n]
    float l_a = __shfl_sync(0xffffffffu, out[3][0], lane & ~3);
    float l_b = __shfl_sync(0xffffffffu, out[3][2], lane & ~3);
    float inva = 1.0f / l_a;
    float invb = 1.0f / l_b;
    int qa = q0 + warp * 16 + g;
    int qb = qa + 8;
    #pragma unroll
    for (int dnt = 0; dnt < 3; dnt++) {
        int c0 = h * HD + dnt * 8 + t * 2;
        float v00 = out[dnt][0] * inva;
        float v01 = out[dnt][1] * inva;
        float v10 = out[dnt][2] * invb;
        float v11 = out[dnt][3] * invb;
        __half h00 = __float2half_rn(v00);
        __half h01 = __float2half_rn(v01);
        __half h10 = __float2half_rn(v10);
        __half h11 = __float2half_rn(v11);
        attH[c0 * NPIX + qa]       = __half_as_ushort(h00);
        attH[(c0 + 1) * NPIX + qa] = __half_as_ushort(h01);
        attH[c0 * NPIX + qb]       = __half_as_ushort(h10);
        attH[(c0 + 1) * NPIX + qb] = __half_as_ushort(h11);
        attL[c0 * NPIX + qa]       = __half_as_ushort(__float2half_rn(v00 - __half2float(h00)));
        attL[(c0 + 1) * NPIX + qa] = __half_as_ushort(__float2half_rn(v01 - __half2float(h01)));
        attL[c0 * NPIX + qb]       = __half_as_ushort(__float2half_rn(v10 - __half2float(h10)));
        attL[(c0 + 1) * NPIX + qb] = __half_as_ushort(__float2half_rn(v11 - __half2float(h11)));
    }
}

// ---------------- launch ----------------
extern "C" void kernel_launch(void* const* d_in, const int* in_sizes, int n_in,
                              void* d_out, int out_size) {
    const float* x      = (const float*)d_in[0];
    const float* gamma  = (const float*)d_in[1];
    const float* beta   = (const float*)d_in[2];
    const float* w_qkv  = (const float*)d_in[3];
    const float* w_dw   = (const float*)d_in[4];
    const float* b_dw   = (const float*)d_in[5];
    const float* w_proj = (const float*)d_in[6];
    const float* temper = (const float*)d_in[7];
    float* out = (float*)d_out;

    float *qkvb, *q32;
    unsigned short *xh, *xl, *wqh, *wql, *wph, *wpl, *ath, *atl, *kh, *kl, *vh;
    cudaGetSymbolAddress((void**)&qkvb, g_qkv);
    cudaGetSymbolAddress((void**)&q32,  g_q32);
    cudaGetSymbolAddress((void**)&xh,   g_xh);
    cudaGetSymbolAddress((void**)&xl,   g_xl);
    cudaGetSymbolAddress((void**)&wqh,  g_wqh);
    cudaGetSymbolAddress((void**)&wql,  g_wql);
    cudaGetSymbolAddress((void**)&wph,  g_wph);
    cudaGetSymbolAddress((void**)&wpl,  g_wpl);
    cudaGetSymbolAddress((void**)&ath,  g_ath);
    cudaGetSymbolAddress((void**)&atl,  g_atl);
    cudaGetSymbolAddress((void**)&kh,   g_kh16);
    cudaGetSymbolAddress((void**)&kl,   g_kl16);
    cudaGetSymbolAddress((void**)&vh,   g_vh16);

    cudaFuncSetAttribute(attn_mma_kernel,
                         cudaFuncAttributeMaxDynamicSharedMemorySize, SMEM_BYTES);

    // 0. weight prepack (independent)
    wprep_kernel<<<(QKV_CH * C_DIM + 255) / 256, 256>>>(w_qkv, w_proj,
                                                        wqh, wql, wph, wpl);

    // 1. LayerNorm -> hi/lo fp16
    ln_kernel<<<NPIX / 256, 256>>>(x, gamma, beta, xh, xl);

    // 2. qkv = w_qkv @ xln   [576,4096] fp32 out (tensor cores)
    {
        dim3 grid(NPIX / 64, QKV_CH / 64);
        gemm16_kernel<<<grid, 128>>>(wqh, wql, xh, xl, nullptr, qkvb,
                                     QKV_CH, C_DIM, NPIX);
    }

    // 3. smem-tiled depthwise 3x3 + bias, fused K/V fp16 prepack
    dwconv_kernel<<<QKV_CH, 256>>>(qkvb, w_dw, b_dw, q32, kh, kl, vh);

    // 4. tensor-core flash attention -> att hi/lo fp16 [192,4096]
    {
        dim3 grid(NPIX / ATT_Q, HEADS);
        attn_mma_kernel<<<grid, 256, SMEM_BYTES>>>(q32, kh, kl, vh, temper,
                                                   ath, atl);
    }

    // 5. out = w_proj @ att + x  (tensor cores)
    {
        dim3 grid(NPIX / 64, C_DIM / 64);
        gemm16_kernel<<<grid, 128>>>(wph, wpl, ath, atl, x, out,
                                     C_DIM, C_DIM, NPIX);
    }
}

// round 15
// speedup vs baseline: 1.2048x; 1.2048x over previous
#include <cuda_runtime.h>
#include <cuda_fp16.h>
#include <cuda_bf16.h>
#include <cstdint>

// Problem constants
#define C_DIM   192
#define HEADS   8
#define HD      24          // head dim = 192/8
#define HH      64
#define WW      64
#define NPIX    4096        // 64*64
#define QKV_CH  576         // 3*C

// ---------------- scratch (static device globals; no allocs) ----------------
__device__ float g_qkv[QKV_CH * NPIX];                // 9 MB (gemm1 out fp32)
__device__ float g_q32[C_DIM * NPIX];                 // 3 MB (dwconv Q out, fp32)
// LN output hi/lo fp16 [c][n]
__device__ unsigned short g_xh[C_DIM * NPIX];
__device__ unsigned short g_xl[C_DIM * NPIX];
// prepacked weights hi/lo fp16 [o][k]
__device__ unsigned short g_wqh[QKV_CH * C_DIM];
__device__ unsigned short g_wql[QKV_CH * C_DIM];
__device__ unsigned short g_wph[C_DIM * C_DIM];
__device__ unsigned short g_wpl[C_DIM * C_DIM];
// attention output hi/lo fp16 [c][n]
__device__ unsigned short g_ath[C_DIM * NPIX];
__device__ unsigned short g_atl[C_DIM * NPIX];
// prepacked K hi/lo fp16, channel-major [c][key] (same layout as V)
__device__ unsigned short g_kh16[C_DIM * NPIX];
__device__ unsigned short g_kl16[C_DIM * NPIX];
__device__ unsigned short g_vh16[C_DIM * NPIX];

// ---------------- small helpers ----------------
__device__ __forceinline__ float ex2f_fast(float x) {
    float r;
    asm("ex2.approx.f32 %0, %1;" : "=f"(r) : "f"(x));
    return r;
}

__device__ __forceinline__ uint32_t h2ex2(uint32_t x) {
    uint32_t r;
    asm("ex2.approx.f16x2 %0, %1;" : "=r"(r) : "r"(x));
    return r;
}

__device__ __forceinline__ void mma16816(float c[4], const uint32_t a[4],
                                         uint32_t b0, uint32_t b1) {
    asm volatile(
        "mma.sync.aligned.m16n8k16.row.col.f32.f16.f16.f32 "
        "{%0,%1,%2,%3}, {%4,%5,%6,%7}, {%8,%9}, {%0,%1,%2,%3};"
        : "+f"(c[0]), "+f"(c[1]), "+f"(c[2]), "+f"(c[3])
        : "r"(a[0]), "r"(a[1]), "r"(a[2]), "r"(a[3]), "r"(b0), "r"(b1));
}

__device__ __forceinline__ void ldsm_x4(uint32_t& r0, uint32_t& r1,
                                        uint32_t& r2, uint32_t& r3, uint32_t addr) {
    asm volatile("ldmatrix.sync.aligned.m8n8.x4.shared.b16 {%0,%1,%2,%3}, [%4];"
                 : "=r"(r0), "=r"(r1), "=r"(r2), "=r"(r3) : "r"(addr));
}

__device__ __forceinline__ void ldsm_x4_t(uint32_t& r0, uint32_t& r1,
                                          uint32_t& r2, uint32_t& r3, uint32_t addr) {
    asm volatile("ldmatrix.sync.aligned.m8n8.x4.trans.shared.b16 {%0,%1,%2,%3}, [%4];"
                 : "=r"(r0), "=r"(r1), "=r"(r2), "=r"(r3) : "r"(addr));
}

__device__ __forceinline__ void cp16(uint32_t dst, const void* src) {
    asm volatile("cp.async.cg.shared.global [%0], [%1], 16;"
                 :: "r"(dst), "l"(src));
}

__device__ __forceinline__ uint32_t packh2(float x, float y) {
    __half2 h = __floats2half2_rn(x, y);
    return *(uint32_t*)&h;
}

// ---------------- Kernel 1: LayerNorm -> hi/lo fp16 [c][n] ----------------
__global__ void ln_kernel(const float* __restrict__ x,
                          const float* __restrict__ gamma,
                          const float* __restrict__ beta,
                          unsigned short* __restrict__ xh,
                          unsigned short* __restrict__ xl) {
    int p = blockIdx.x * blockDim.x + threadIdx.x;
    if (p >= NPIX) return;
    float s = 0.f, s2 = 0.f;
    #pragma unroll 8
    for (int c = 0; c < C_DIM; c++) {
        float v = x[c * NPIX + p];
        s += v;
        s2 = fmaf(v, v, s2);
    }
    const float invC = 1.0f / (float)C_DIM;
    float mean = s * invC;
    float var = s2 * invC - mean * mean;
    float inv = rsqrtf(var + 1e-5f);
    #pragma unroll 8
    for (int c = 0; c < C_DIM; c++) {
        float v = (x[c * NPIX + p] - mean) * inv;
        v = fmaf(v, gamma[c], beta[c]);
        __half h = __float2half_rn(v);
        xh[c * NPIX + p] = __half_as_ushort(h);
        xl[c * NPIX + p] = __half_as_ushort(__float2half_rn(v - __half2float(h)));
    }
}

// ---------------- Kernel 1b: weight prepack (hi/lo fp16 split) ----------------
__global__ void wprep_kernel(const float* __restrict__ wq, const float* __restrict__ wp,
                             unsigned short* __restrict__ wqh, unsigned short* __restrict__ wql,
                             unsigned short* __restrict__ wph, unsigned short* __restrict__ wpl) {
    int i = blockIdx.x * 256 + threadIdx.x;
    if (i < QKV_CH * C_DIM) {
        float v = wq[i];
        __half h = __float2half_rn(v);
        wqh[i] = __half_as_ushort(h);
        wql[i] = __half_as_ushort(__float2half_rn(v - __half2float(h)));
    }
    if (i < C_DIM * C_DIM) {
        float v = wp[i];
        __half h = __float2half_rn(v);
        wph[i] = __half_as_ushort(h);
        wpl[i] = __half_as_ushort(__float2half_rn(v - __half2float(h)));
    }
}

// ---------------- Kernel 2: tensor-core GEMM (hi/lo fp16 compensated) ----------
__global__ __launch_bounds__(128) void gemm16_kernel(
        const unsigned short* __restrict__ Wh,
        const unsigned short* __restrict__ Wl,
        const unsigned short* __restrict__ Bh,
        const unsigned short* __restrict__ Bl,
        const float* __restrict__ resid,
        float* __restrict__ Y,
        int O, int K, int N) {
    __shared__ __align__(16) __half Wsh[64][40];
    __shared__ __align__(16) __half Wsl[64][40];
    __shared__ __align__(16) __half Xsh[32][72];
    __shared__ __align__(16) __half Xsl[32][72];
    const int tid = threadIdx.x;
    const int lane = tid & 31, warp = tid >> 5;
    const int g = lane >> 2, t = lane & 3;
    const int o0 = blockIdx.y * 64, n0 = blockIdx.x * 64;

    float acc[8][4];
    #pragma unroll
    for (int i = 0; i < 8; i++)
        #pragma unroll
        for (int j = 0; j < 4; j++) acc[i][j] = 0.f;

    const uint32_t xh_base = (uint32_t)__cvta_generic_to_shared(&Xsh[0][0])
                             + (uint32_t)(lane * 72) * 2;
    const uint32_t xl_base = (uint32_t)__cvta_generic_to_shared(&Xsl[0][0])
                             + (uint32_t)(lane * 72) * 2;

    for (int k0 = 0; k0 < K; k0 += 32) {
        if (k0) __syncthreads();
        {
            int row = tid >> 2, seg = tid & 3;
            #pragma unroll
            for (int rr = 0; rr < 2; rr++) {
                int r = row + rr * 32;
                *(uint4*)&Wsh[r][seg * 8] =
                    *(const uint4*)&Wh[(size_t)(o0 + r) * K + k0 + seg * 8];
                *(uint4*)&Wsl[r][seg * 8] =
                    *(const uint4*)&Wl[(size_t)(o0 + r) * K + k0 + seg * 8];
            }
            int xr = tid >> 3, xseg = tid & 7;
            #pragma unroll
            for (int rr = 0; rr < 2; rr++) {
                int k = xr + rr * 16;
                *(uint4*)&Xsh[k][xseg * 8] =
                    *(const uint4*)&Bh[(size_t)(k0 + k) * N + n0 + xseg * 8];
                *(uint4*)&Xsl[k][xseg * 8] =
                    *(const uint4*)&Bl[(size_t)(k0 + k) * N + n0 + xseg * 8];
            }
        }
        __syncthreads();

        uint32_t awh[2][4], awl[2][4];
        const int orr = warp * 16 + g;
        #pragma unroll
        for (int ks = 0; ks < 2; ks++) {
            int db = ks * 16 + t * 2;
            awh[ks][0] = *(const uint32_t*)&Wsh[orr][db];
            awh[ks][1] = *(const uint32_t*)&Wsh[orr + 8][db];
            awh[ks][2] = *(const uint32_t*)&Wsh[orr][db + 8];
            awh[ks][3] = *(const uint32_t*)&Wsh[orr + 8][db + 8];
            awl[ks][0] = *(const uint32_t*)&Wsl[orr][db];
            awl[ks][1] = *(const uint32_t*)&Wsl[orr + 8][db];
            awl[ks][2] = *(const uint32_t*)&Wsl[orr][db + 8];
            awl[ks][3] = *(const uint32_t*)&Wsl[orr + 8][db + 8];
        }
        #pragma unroll
        for (int nt = 0; nt < 8; nt++) {
            uint32_t bh0, bh1, bh2, bh3, bl0, bl1, bl2, bl3;
            ldsm_x4_t(bh0, bh1, bh2, bh3, xh_base + nt * 16);
            ldsm_x4_t(bl0, bl1, bl2, bl3, xl_base + nt * 16);
            mma16816(acc[nt], awh[0], bh0, bh1);
            mma16816(acc[nt], awh[1], bh2, bh3);
            mma16816(acc[nt], awh[0], bl0, bl1);
            mma16816(acc[nt], awh[1], bl2, bl3);
            mma16816(acc[nt], awl[0], bh0, bh1);
            mma16816(acc[nt], awl[1], bh2, bh3);
        }
    }

    const int orr = warp * 16 + g;
    #pragma unroll
    for (int nt = 0; nt < 8; nt++) {
        #pragma unroll
        for (int rr = 0; rr < 2; rr++) {
            int o = o0 + orr + rr * 8;
            int n = n0 + nt * 8 + t * 2;
            float v0 = acc[nt][rr * 2 + 0];
            float v1 = acc[nt][rr * 2 + 1];
            if (resid) {
                float2 rv = *(const float2*)&resid[(size_t)o * N + n];
                v0 += rv.x; v1 += rv.y;
            }
            float2 w2 = make_float2(v0, v1);
            *(float2*)&Y[(size_t)o * N + n] = w2;
        }
    }
}

// ---------------- Kernel 3: depthwise 3x3 conv, 4 pixels/thread ----------
// All K/V outputs channel-major [c][key] -> fully coalesced vector stores.
__global__ void dwconv_kernel(const float* __restrict__ in,
                              const float* __restrict__ w,
                              const float* __restrict__ b,
                              float* __restrict__ qout,
                              unsigned short* __restrict__ kh,
                              unsigned short* __restrict__ kl,
                              unsigned short* __restrict__ vh) {
    int idx = blockIdx.x * blockDim.x + threadIdx.x;   // over QKV_CH*1024
    if (idx >= QKV_CH * 1024) return;
    int ch = idx >> 10;
    int pg = idx & 1023;
    int yy = pg >> 4;              // row 0..63
    int xs = (pg & 15) * 4;        // col start (aligned 4)
    const float* base = in + (size_t)ch * NPIX;

    float r[3][6];
    #pragma unroll
    for (int dy = 0; dy < 3; dy++) {
        int y2 = yy + dy - 1;
        if (y2 < 0 || y2 >= HH) {
            #pragma unroll
            for (int j = 0; j < 6; j++) r[dy][j] = 0.f;
        } else {
            const float* rp = base + y2 * WW + xs;
            float4 m = *(const float4*)rp;
            r[dy][1] = m.x; r[dy][2] = m.y; r[dy][3] = m.z; r[dy][4] = m.w;
            r[dy][0] = (xs > 0) ? rp[-1] : 0.f;
            r[dy][5] = (xs + 4 < WW) ? rp[4] : 0.f;
        }
    }

    const float* wp = &w[ch * 9];
    float bias = b[ch];
    float acc[4];
    #pragma unroll
    for (int k = 0; k < 4; k++) {
        float a = bias;
        #pragma unroll
        for (int dy = 0; dy < 3; dy++)
            #pragma unroll
            for (int dx = 0; dx < 3; dx++)
                a = fmaf(r[dy][k + dx], wp[dy * 3 + dx], a);
        acc[k] = a;
    }

    int p0 = yy * WW + xs;
    if (ch < C_DIM) {
        *(float4*)&qout[(size_t)ch * NPIX + p0] =
            make_float4(acc[0], acc[1], acc[2], acc[3]);
    } else if (ch < 2 * C_DIM) {
        int cc = ch - C_DIM;
        __half h0 = __float2half_rn(acc[0]);
        __half h1 = __float2half_rn(acc[1]);
        __half h2 = __float2half_rn(acc[2]);
        __half h3 = __float2half_rn(acc[3]);
        uint2 hp;
        hp.x = ((uint32_t)__half_as_ushort(h1) << 16) | __half_as_ushort(h0);
        hp.y = ((uint32_t)__half_as_ushort(h3) << 16) | __half_as_ushort(h2);
        *(uint2*)&kh[(size_t)cc * NPIX + p0] = hp;
        uint2 lp;
        lp.x = packh2(acc[0] - __half2float(h0), acc[1] - __half2float(h1));
        lp.y = packh2(acc[2] - __half2float(h2), acc[3] - __half2float(h3));
        *(uint2*)&kl[(size_t)cc * NPIX + p0] = lp;
    } else {
        uint2 vp;
        vp.x = packh2(acc[0], acc[1]);
        vp.y = packh2(acc[2], acc[3]);
        *(uint2*)&vh[(size_t)(ch - 2 * C_DIM) * NPIX + p0] = vp;
    }
}

// ---------------- Kernel 4: tensor-core flash attention ----------------
// K now [d][key] in smem (like V); K B-fragments via ldmatrix.x4.trans
// (the gemm16-validated pattern). Rows d24..31 zeroed once per buffer.
#define ATT_Q  128
#define ATT_K  128
#define NCHUNK (NPIX / ATT_K)         // 32

#define OKB  0
#define KBUF 8704                     // hi [32][136] + lo [32][136]
#define OVB  (3 * KBUF)               // 26112
#define VBUF 4352                     // [32][136]
#define SM_HALVES (OVB + 3 * VBUF)    // 39168
#define SMEM_BYTES (SM_HALVES * 2)    // 78336

__global__ __launch_bounds__(256, 2) void attn_mma_kernel(
        const float* __restrict__ q32,
        const unsigned short* __restrict__ kh,
        const unsigned short* __restrict__ kl,
        const unsigned short* __restrict__ vh,
        const float* __restrict__ temp,
        unsigned short* __restrict__ attH,
        unsigned short* __restrict__ attL) {
    extern __shared__ __align__(16) __half sm[];
    const int tid = threadIdx.x;
    const int lane = tid & 31;
    const int warp = tid >> 5;
    const int g = lane >> 2;
    const int t = lane & 3;

    const int h = blockIdx.y;
    const int q0 = blockIdx.x * ATT_Q;
    const float scale = temp[h] * 1.4426950408889634f;

    const float* qg = q32 + (h * HD) * NPIX;
    const unsigned short* khg = kh + (size_t)(h * HD) * NPIX;
    const unsigned short* klg = kl + (size_t)(h * HD) * NPIX;
    const unsigned short* vg  = vh + (size_t)(h * HD) * NPIX;

    const uint32_t smb = (uint32_t)__cvta_generic_to_shared(sm);

    // one-time init: K rows 24..31 (hi+lo, all bufs) = 0; V rows 24..31
    // (row 24 = ones, rest 0)
    {
        // K pads: 3 bufs x 2 parts x 8 rows x 136 cols = 6528
        for (int i = tid; i < 6528; i += 256) {
            int buf = i / 2176;
            int rem = i - buf * 2176;
            int part = rem / 1088;
            int rr = rem - part * 1088;
            int row = rr / 136;
            int col = rr - row * 136;
            sm[OKB + buf * KBUF + part * 4352 + (24 + row) * 136 + col] =
                __ushort_as_half(0);
        }
        for (int i = tid; i < 3 * 8 * 136; i += 256) {
            int buf = i / 1088;
            int rem = i - buf * 1088;
            int row = rem / 136;
            int col = rem - row * 136;
            sm[OVB + buf * VBUF + (24 + row) * 136 + col] =
                (row == 0) ? __float2half_rn(1.0f) : __ushort_as_half(0);
        }
    }

    // cp.async: K hi / K lo / V all share the [c][key] global layout
    auto issue_chunk = [&](int b, int m0) {
        uint32_t kdstH = smb + (OKB + b * KBUF) * 2;
        uint32_t kdstL = kdstH + 4352 * 2;
        uint32_t vdst  = smb + (OVB + b * VBUF) * 2;
        #pragma unroll
        for (int i = tid; i < 1152; i += 256) {
            int seg = i / 384;            // 0=Kh, 1=Kl, 2=V
            int r = i - seg * 384;
            int d = r >> 4;               // 0..23
            int c2 = r & 15;              // 16 x 8-key groups
            const unsigned short* srcb = (seg == 0) ? khg : (seg == 1) ? klg : vg;
            uint32_t dstb = (seg == 0) ? kdstH : (seg == 1) ? kdstL : vdst;
            cp16(dstb + (d * 136 + c2 * 8) * 2,
                 srcb + (size_t)d * NPIX + m0 + c2 * 8);
        }
        asm volatile("cp.async.commit_group;" ::: "memory");
    };
    issue_chunk(0, 0);
    issue_chunk(1, ATT_K);

    // Q A-fragments directly from global
    uint32_t aqh[2][4], aql[2][4];
    const int qr = warp * 16 + g;
    #pragma unroll
    for (int ks = 0; ks < 2; ks++) {
        #pragma unroll
        for (int r = 0; r < 4; r++) {
            int d0 = ks * 16 + t * 2 + ((r >= 2) ? 8 : 0);
            int qq = q0 + qr + (r & 1) * 8;
            if (d0 < HD) {
                float v0 = qg[d0 * NPIX + qq] * scale;
                float v1 = qg[(d0 + 1) * NPIX + qq] * scale;
                __half h0 = __float2half_rn(v0);
                __half h1 = __float2half_rn(v1);
                aqh[ks][r] = ((uint32_t)__half_as_ushort(h1) << 16) |
                             __half_as_ushort(h0);
                __half l0 = __float2half_rn(v0 - __half2float(h0));
                __half l1 = __float2half_rn(v1 - __half2float(h1));
                aql[ks][r] = ((uint32_t)__half_as_ushort(l1) << 16) |
                             __half_as_ushort(l0);
            } else {
                aqh[ks][r] = 0;
                aql[ks][r] = 0;
            }
        }
    }

    const int l7 = lane & 7;
    const int grp = lane >> 3;
    const uint32_t loff_kt = (uint32_t)lane * 272;          // K: x4_t row addr
    const uint32_t loff_v  = (l7 * 136 + grp * 8) * 2;      // V: plain x4

    float out[4][4];
    #pragma unroll
    for (int i = 0; i < 4; i++)
        #pragma unroll
        for (int j = 0; j < 4; j++) out[i][j] = 0.f;
    float m_a = -1e30f, m_b = -1e30f;

    for (int ch = 0; ch < NCHUNK; ch++) {
        if (ch < NCHUNK - 1)
            asm volatile("cp.async.wait_group 1;" ::: "memory");
        else
            asm volatile("cp.async.wait_group 0;" ::: "memory");
        __syncthreads();
        if (ch + 2 < NCHUNK) issue_chunk((ch + 2) % 3, (ch + 2) * ATT_K);

        const int b = ch % 3;
        const uint32_t kbase = smb + (OKB + b * KBUF) * 2;
        const uint32_t vbase = smb + (OVB + b * VBUF) * 2;

        #pragma unroll
        for (int hc = 0; hc < 2; hc++) {
            const uint32_t kaddr_h = kbase + loff_kt + (uint32_t)hc * 128;
            const uint32_t kaddr_l = kaddr_h + 4352 * 2;
            const uint32_t vaddr   = vbase + (uint32_t)hc * 128 + loff_v;

            float s[8][4];
            #pragma unroll
            for (int nt = 0; nt < 8; nt++) {
                uint32_t h0, h1, h2, h3, L0, L1, L2, L3;
                ldsm_x4_t(h0, h1, h2, h3, kaddr_h + nt * 16);
                ldsm_x4_t(L0, L1, L2, L3, kaddr_l + nt * 16);
                s[nt][0] = s[nt][1] = s[nt][2] = s[nt][3] = 0.f;
                mma16816(s[nt], aqh[0], h0, h1);
                mma16816(s[nt], aqh[1], h2, h3);
                mma16816(s[nt], aql[0], h0, h1);
                mma16816(s[nt], aql[1], h2, h3);
                mma16816(s[nt], aqh[0], L0, L1);
                mma16816(s[nt], aqh[1], L2, L3);
            }

            float ra = -1e30f, rb = -1e30f;
            #pragma unroll
            for (int nt = 0; nt < 8; nt++) {
                ra = fmaxf(ra, fmaxf(s[nt][0], s[nt][1]));
                rb = fmaxf(rb, fmaxf(s[nt][2], s[nt][3]));
            }
            ra = fmaxf(ra, __shfl_xor_sync(0xffffffffu, ra, 1));
            ra = fmaxf(ra, __shfl_xor_sync(0xffffffffu, ra, 2));
            rb = fmaxf(rb, __shfl_xor_sync(0xffffffffu, rb, 1));
            rb = fmaxf(rb, __shfl_xor_sync(0xffffffffu, rb, 2));
            float nma = fmaxf(m_a, ra);
            float nmb = fmaxf(m_b, rb);
            float ala = ex2f_fast(m_a - nma);
            float alb = ex2f_fast(m_b - nmb);
            m_a = nma; m_b = nmb;
            #pragma unroll
            for (int dnt = 0; dnt < 4; dnt++) {
                out[dnt][0] *= ala; out[dnt][1] *= ala;
                out[dnt][2] *= alb; out[dnt][3] *= alb;
            }

            uint32_t pa[4][4];
            #pragma unroll
            for (int kv = 0; kv < 4; kv++) {
                pa[kv][0] = h2ex2(packh2(s[2 * kv][0] - m_a,     s[2 * kv][1] - m_a));
                pa[kv][1] = h2ex2(packh2(s[2 * kv][2] - m_b,     s[2 * kv][3] - m_b));
                pa[kv][2] = h2ex2(packh2(s[2 * kv + 1][0] - m_a, s[2 * kv + 1][1] - m_a));
                pa[kv][3] = h2ex2(packh2(s[2 * kv + 1][2] - m_b, s[2 * kv + 1][3] - m_b));
            }

            #pragma unroll
            for (int dnt = 0; dnt < 4; dnt++) {
                uint32_t base = vaddr + (uint32_t)(dnt * 8) * 272;
                uint32_t v0, v1, v2, v3, v4, v5, v6, v7;
                ldsm_x4(v0, v1, v2, v3, base);
                ldsm_x4(v4, v5, v6, v7, base + 64);
                mma16816(out[dnt], pa[0], v0, v1);
                mma16816(out[dnt], pa[1], v2, v3);
                mma16816(out[dnt], pa[2], v4, v5);
                mma16816(out[dnt], pa[3], v6, v7);
            }
        }
    }

    // epilogue: normalize, split hi/lo, store [c][n]
    float l_a = __shfl_sync(0xffffffffu, out[3][0], lane & ~3);
    float l_b = __shfl_sync(0xffffffffu, out[3][2], lane & ~3);
    float inva = 1.0f / l_a;
    float invb = 1.0f / l_b;
    int qa = q0 + warp * 16 + g;
    int qb = qa + 8;
    #pragma unroll
    for (int dnt = 0; dnt < 3; dnt++) {
        int c0 = h * HD + dnt * 8 + t * 2;
        float v00 = out[dnt][0] * inva;
        float v01 = out[dnt][1] * inva;
        float v10 = out[dnt][2] * invb;
        float v11 = out[dnt][3] * invb;
        __half h00 = __float2half_rn(v00);
        __half h01 = __float2half_rn(v01);
        __half h10 = __float2half_rn(v10);
        __half h11 = __float2half_rn(v11);
        attH[c0 * NPIX + qa]       = __half_as_ushort(h00);
        attH[(c0 + 1) * NPIX + qa] = __half_as_ushort(h01);
        attH[c0 * NPIX + qb]       = __half_as_ushort(h10);
        attH[(c0 + 1) * NPIX + qb] = __half_as_ushort(h11);
        attL[c0 * NPIX + qa]       = __half_as_ushort(__float2half_rn(v00 - __half2float(h00)));
        attL[(c0 + 1) * NPIX + qa] = __half_as_ushort(__float2half_rn(v01 - __half2float(h01)));
        attL[c0 * NPIX + qb]       = __half_as_ushort(__float2half_rn(v10 - __half2float(h10)));
        attL[(c0 + 1) * NPIX + qb] = __half_as_ushort(__float2half_rn(v11 - __half2float(h11)));
    }
}

// ---------------- launch ----------------
extern "C" void kernel_launch(void* const* d_in, const int* in_sizes, int n_in,
                              void* d_out, int out_size) {
    const float* x      = (const float*)d_in[0];
    const float* gamma  = (const float*)d_in[1];
    const float* beta   = (const float*)d_in[2];
    const float* w_qkv  = (const float*)d_in[3];
    const float* w_dw   = (const float*)d_in[4];
    const float* b_dw   = (const float*)d_in[5];
    const float* w_proj = (const float*)d_in[6];
    const float* temper = (const float*)d_in[7];
    float* out = (float*)d_out;

    float *qkvb, *q32;
    unsigned short *xh, *xl, *wqh, *wql, *wph, *wpl, *ath, *atl, *kh, *kl, *vh;
    cudaGetSymbolAddress((void**)&qkvb, g_qkv);
    cudaGetSymbolAddress((void**)&q32,  g_q32);
    cudaGetSymbolAddress((void**)&xh,   g_xh);
    cudaGetSymbolAddress((void**)&xl,   g_xl);
    cudaGetSymbolAddress((void**)&wqh,  g_wqh);
    cudaGetSymbolAddress((void**)&wql,  g_wql);
    cudaGetSymbolAddress((void**)&wph,  g_wph);
    cudaGetSymbolAddress((void**)&wpl,  g_wpl);
    cudaGetSymbolAddress((void**)&ath,  g_ath);
    cudaGetSymbolAddress((void**)&atl,  g_atl);
    cudaGetSymbolAddress((void**)&kh,   g_kh16);
    cudaGetSymbolAddress((void**)&kl,   g_kl16);
    cudaGetSymbolAddress((void**)&vh,   g_vh16);

    cudaFuncSetAttribute(attn_mma_kernel,
                         cudaFuncAttributeMaxDynamicSharedMemorySize, SMEM_BYTES);

    // 0. weight prepack (independent)
    wprep_kernel<<<(QKV_CH * C_DIM + 255) / 256, 256>>>(w_qkv, w_proj,
                                                        wqh, wql, wph, wpl);

    // 1. LayerNorm -> hi/lo fp16
    ln_kernel<<<NPIX / 256, 256>>>(x, gamma, beta, xh, xl);

    // 2. qkv = w_qkv @ xln   [576,4096] fp32 out (tensor cores)
    {
        dim3 grid(NPIX / 64, QKV_CH / 64);
        gemm16_kernel<<<grid, 128>>>(wqh, wql, xh, xl, nullptr, qkvb,
                                     QKV_CH, C_DIM, NPIX);
    }

    // 3. depthwise 3x3 + bias, 4 px/thread, coalesced K/V fp16 prepack
    dwconv_kernel<<<(QKV_CH * 1024) / 256, 256>>>(qkvb, w_dw, b_dw,
                                                  q32, kh, kl, vh);

    // 4. tensor-core flash attention -> att hi/lo fp16 [192,4096]
    {
        dim3 grid(NPIX / ATT_Q, HEADS);
        attn_mma_kernel<<<grid, 256, SMEM_BYTES>>>(q32, kh, kl, vh, temper,
                                                   ath, atl);
    }

    // 5. out = w_proj @ att + x  (tensor cores)
    {
        dim3 grid(NPIX / 64, C_DIM / 64);
        gemm16_kernel<<<grid, 128>>>(wph, wpl, ath, atl, x, out,
                                     C_DIM, C_DIM, NPIX);
    }
}